// round 11
// baseline (speedup 1.0000x reference)
#include <cuda_runtime.h>
#include <cuda_fp16.h>

typedef unsigned int u32;
typedef unsigned long long u64;

#define BT 128
#define ROWB 496                 // 496 mod 128 = 112 -> conflict-free ldmatrix
#define MSLOT 240                // M slots start in each element row
// fp32 scalar region (float indices)
#define SF_WF 0                  // 6 x 20
#define SF_BF 120                // 20
#define SF_WR 140                // 5 x 24 (zero-padded)
#define SF_BM 260                // 24
#define SF_BU 284                // 24
#define SF_BR 308
// fp16 B matrices, byte offsets ([32][24] each, zero rows 18-31)
#define WM1_OFF 1248
#define WM2_OFF (WM1_OFF + 1536)
#define WUH_OFF (WM2_OFF + 1536)
#define WUM_OFF (WUH_OFF + 1536)
#define ACT_OFF (WUM_OFF + 1536)          // 7392 (16B aligned)
#define SMEM_BYTES (ACT_OFF + BT*ROWB)    // 70880 -> 3 CTAs/SM

static __device__ __forceinline__ u64 dup2(float v){
    u64 r; asm("mov.b64 %0, {%1,%1};" : "=l"(r) : "f"(v)); return r;
}
static __device__ __forceinline__ void upk2(u64 v, float& lo, float& hi){
    asm("mov.b64 {%0,%1}, %2;" : "=f"(lo), "=f"(hi) : "l"(v));
}
static __device__ __forceinline__ u64 fma2(u64 a, u64 b, u64 c){
    u64 d; asm("fma.rn.f32x2 %0, %1, %2, %3;" : "=l"(d) : "l"(a), "l"(b), "l"(c));
    return d;
}
static __device__ __forceinline__ float tanhap(float x){
    float r; asm("tanh.approx.f32 %0, %1;" : "=f"(r) : "f"(x)); return r;
}
static __device__ __forceinline__ void ldrow9(const float* s, int off, u64 w[9]){
    ulonglong2 q0 = *(const ulonglong2*)(s + off);
    ulonglong2 q1 = *(const ulonglong2*)(s + off + 4);
    ulonglong2 q2 = *(const ulonglong2*)(s + off + 8);
    ulonglong2 q3 = *(const ulonglong2*)(s + off + 12);
    w[0]=q0.x; w[1]=q0.y; w[2]=q1.x; w[3]=q1.y;
    w[4]=q2.x; w[5]=q2.y; w[6]=q3.x; w[7]=q3.y;
    w[8] = *(const u64*)(s + off + 16);
}
static __device__ __forceinline__ void ldm4(u32 addr, u32 a[4]){
    asm volatile("ldmatrix.sync.aligned.m8n8.x4.shared.b16 {%0,%1,%2,%3}, [%4];"
        : "=r"(a[0]),"=r"(a[1]),"=r"(a[2]),"=r"(a[3]) : "r"(addr));
}
static __device__ __forceinline__ void mmas(float d[4], const u32 a[4], const u32 b[2]){
    asm volatile("mma.sync.aligned.m16n8k16.row.col.f32.f16.f16.f32 "
        "{%0,%1,%2,%3}, {%4,%5,%6,%7}, {%8,%9}, {%0,%1,%2,%3};"
        : "+f"(d[0]),"+f"(d[1]),"+f"(d[2]),"+f"(d[3])
        : "r"(a[0]),"r"(a[1]),"r"(a[2]),"r"(a[3]), "r"(b[0]),"r"(b[1]));
}
// B fragment (m16n8k16 .col): reg0={B[k0][n],B[k0+1][n]}, reg1={B[k0+8][n],B[k0+9][n]}
static __device__ __forceinline__ void ldbfrag(const __half* W, int ks, int nf, int lane, u32 r[2]){
    int k0 = ks*16 + (lane & 3)*2;
    int nn = nf*8 + (lane >> 2);
    u32 a = __half_as_ushort(W[k0*24 + nn]);
    u32 b = __half_as_ushort(W[(k0+1)*24 + nn]);
    u32 c = __half_as_ushort(W[(k0+8)*24 + nn]);
    u32 d = __half_as_ushort(W[(k0+9)*24 + nn]);
    r[0] = a | (b << 16);
    r[1] = c | (d << 16);
}

__global__ void __launch_bounds__(BT, 3) mp_kernel(
    const float* __restrict__ x,
    const float* __restrict__ Wf, const float* __restrict__ bf,
    const float* __restrict__ Wm, const float* __restrict__ bm,
    const float* __restrict__ Wu, const float* __restrict__ bu,
    const float* __restrict__ Wr, const float* __restrict__ br,
    float* __restrict__ out, int n)
{
    extern __shared__ __align__(16) char smc[];
    float* sf = (float*)smc;
    const int t = threadIdx.x;

    // ---- zero activation region (all pads MUST be zero for the mma path) ----
    for (int i = t; i < (BT*ROWB)/16; i += BT)
        *(uint4*)(smc + ACT_OFF + i*16) = make_uint4(0,0,0,0);

    // ---- fp32 scalars ----
    for (int k = t; k < 120; k += BT){ int r=k/20, c=k%20; sf[SF_WF+k] = (c<18)? Wf[r*18+c] : 0.f; }
    for (int k = t; k < 20;  k += BT) sf[SF_BF+k] = (k<18)? bf[k] : 0.f;
    for (int k = t; k < 120; k += BT){ int r=k/24, c=k%24; sf[SF_WR+k] = (c<18)? Wr[r*18+c] : 0.f; }
    for (int k = t; k < 24;  k += BT){ sf[SF_BM+k] = (k<18)? bm[k] : 0.f;
                                       sf[SF_BU+k] = (k<18)? bu[k] : 0.f; }
    if (t == 0) sf[SF_BR] = br[0];

    // ---- fp16 B matrices [32][24], rows 18-31 zero ----
    for (int idx = t; idx < 32*24; idx += BT){
        int k = idx/24, nn = idx%24;
        float v1=0.f, v2=0.f, vh=0.f, vm=0.f;
        if (k < 18 && nn < 18){
            v1 = Wm[k*18 + nn];                               // h_i part
            v2 = Wm[(18+k)*18 + nn];                          // h_{i+1} part
            vh = Wu[(18+k)*18 + nn] + Wu[(36+k)*18 + nn];     // folded (U==h)
            vm = Wu[k*18 + nn];
        }
        ((__half*)(smc + WM1_OFF))[idx] = __float2half(v1);
        ((__half*)(smc + WM2_OFF))[idx] = __float2half(v2);
        ((__half*)(smc + WUH_OFF))[idx] = __float2half(vh);
        ((__half*)(smc + WUM_OFF))[idx] = __float2half(vm);
    }
    __syncthreads();

    // ================= layer 1: SIMT fp32, thread = element =================
    int e = blockIdx.x * BT + t;
    if (e >= n) e = n - 1;                    // clamp; no early return (warp-collective mma later)
    {
        float xv[30];
        const float2* xb = (const float2*)(x + (long long)e * 30);
        #pragma unroll
        for (int k = 0; k < 15; k++){ float2 v = xb[k]; xv[2*k]=v.x; xv[2*k+1]=v.y; }

        u64 acc[5][9];
        {
            u64 bb[9]; ldrow9(sf, SF_BF, bb);
            #pragma unroll
            for (int p = 0; p < 9; p++){
                #pragma unroll
                for (int i = 0; i < 5; i++) acc[i][p] = bb[p];
            }
        }
        #pragma unroll
        for (int f = 0; f < 6; f++){
            u64 w[9]; ldrow9(sf, SF_WF + f*20, w);
            #pragma unroll
            for (int i = 0; i < 5; i++){
                u64 a = dup2(xv[i*6 + f]);
                #pragma unroll
                for (int p = 0; p < 9; p++) acc[i][p] = fma2(a, w[p], acc[i][p]);
            }
        }
        char* row = smc + ACT_OFF + t*ROWB;
        #pragma unroll
        for (int i = 0; i < 5; i++){
            u32 hp[9];
            #pragma unroll
            for (int p = 0; p < 9; p++){
                float lo, hi; upk2(acc[i][p], lo, hi);
                __half2 h2 = __floats2half2_rn(tanhap(lo), tanhap(hi));
                hp[p] = *(u32*)&h2;
            }
            *(uint4*)(row + i*48)      = make_uint4(hp[0],hp[1],hp[2],hp[3]);
            *(uint4*)(row + i*48 + 16) = make_uint4(hp[4],hp[5],hp[6],hp[7]);
            *(u32*) (row + i*48 + 32)  = hp[8];
        }
    }
    __syncwarp();

    // ================= MMA phase: warp = 2 tiles of 16 elements =================
    const int lane = t & 31;
    const int w    = t >> 5;

    // B fragments: 2 k-chunks x 3 n-frags each
    u32 Bm1[2][3][2], Bm2[2][3][2], Bh[2][3][2], Bu2[2][3][2];
    {
        const __half* W1 = (const __half*)(smc + WM1_OFF);
        const __half* W2 = (const __half*)(smc + WM2_OFF);
        const __half* WH = (const __half*)(smc + WUH_OFF);
        const __half* WM = (const __half*)(smc + WUM_OFF);
        #pragma unroll
        for (int ks = 0; ks < 2; ks++)
            #pragma unroll
            for (int nf = 0; nf < 3; nf++){
                ldbfrag(W1, ks, nf, lane, Bm1[ks][nf]);
                ldbfrag(W2, ks, nf, lane, Bm2[ks][nf]);
                ldbfrag(WH, ks, nf, lane, Bh[ks][nf]);
                ldbfrag(WM, ks, nf, lane, Bu2[ks][nf]);
            }
    }
    // bias pairs per n-fragment
    float bmv[3][2], buv[3][2];
    #pragma unroll
    for (int nf = 0; nf < 3; nf++){
        int c = nf*8 + (lane & 3)*2;
        bmv[nf][0] = sf[SF_BM + c]; bmv[nf][1] = sf[SF_BM + c + 1];
        buv[nf][0] = sf[SF_BU + c]; buv[nf][1] = sf[SF_BU + c + 1];
    }
    const float brv = sf[SF_BR];

    const u32 smem_base = (u32)__cvta_generic_to_shared(smc);
    const int lrow = lane & 15;
    const int lcol = (lane >> 4) << 4;     // 16B col window select

    #pragma unroll
    for (int tl = 0; tl < 2; tl++){
        const int rowbase = w*32 + tl*16;
        u32 ab = smem_base + ACT_OFF + rowbase*ROWB + lrow*ROWB + lcol;
        char* tgen = smc + ACT_OFF + rowbase*ROWB;

        // ---- M layer: M_i = tanh(h_i @ Wm1 + h_{i+1} @ Wm2 + bm) -> M slot (i+1) ----
        #pragma unroll
        for (int i = 0; i < 5; i++){
            const int ip = (i + 1) % 5;
            u32 a0[4], a1[4], b0[4], b1[4];
            ldm4(ab + i*48,       a0);     // h_i   k0-15
            ldm4(ab + i*48  + 32, a1);     // h_i   k16-31 (pad/overrun x zero B rows)
            ldm4(ab + ip*48,      b0);     // h_{i+1}
            ldm4(ab + ip*48 + 32, b1);
            float d[3][4];
            #pragma unroll
            for (int nf = 0; nf < 3; nf++){
                d[nf][0]=bmv[nf][0]; d[nf][1]=bmv[nf][1];
                d[nf][2]=bmv[nf][0]; d[nf][3]=bmv[nf][1];
                mmas(d[nf], a0, Bm1[0][nf]);
                mmas(d[nf], a1, Bm1[1][nf]);
                mmas(d[nf], b0, Bm2[0][nf]);
                mmas(d[nf], b1, Bm2[1][nf]);
            }
            char* dst = tgen + MSLOT + ip*48;
            int r = lane >> 2;
            #pragma unroll
            for (int nf = 0; nf < 3; nf++){
                int c = nf*8 + (lane & 3)*2;
                if (c < 18){
                    __half2 lo = __floats2half2_rn(tanhap(d[nf][0]), tanhap(d[nf][1]));
                    __half2 hi = __floats2half2_rn(tanhap(d[nf][2]), tanhap(d[nf][3]));
                    *(__half2*)(dst + r*ROWB + c*2)     = lo;
                    *(__half2*)(dst + (r+8)*ROWB + c*2) = hi;
                }
            }
        }
        __syncwarp();

        // ---- U layer + readout: U_i = tanh(M_{i-1}@WuM + h_i@WuH + bu) ----
        float pr = 0.f, pr8 = 0.f;
        #pragma unroll
        for (int i = 0; i < 5; i++){
            u32 h0[4], h1[4], m0[4], m1[4];
            ldm4(ab + i*48,              h0);
            ldm4(ab + i*48 + 32,         h1);
            ldm4(ab + MSLOT + i*48,      m0);   // M slot i holds M_{i-1}
            ldm4(ab + MSLOT + i*48 + 32, m1);
            float d[3][4];
            #pragma unroll
            for (int nf = 0; nf < 3; nf++){
                d[nf][0]=buv[nf][0]; d[nf][1]=buv[nf][1];
                d[nf][2]=buv[nf][0]; d[nf][3]=buv[nf][1];
                mmas(d[nf], h0, Bh[0][nf]);
                mmas(d[nf], h1, Bh[1][nf]);
                mmas(d[nf], m0, Bu2[0][nf]);
                mmas(d[nf], m1, Bu2[1][nf]);
            }
            #pragma unroll
            for (int nf = 0; nf < 3; nf++){
                int c = nf*8 + (lane & 3)*2;
                float w0 = sf[SF_WR + i*24 + c];
                float w1 = sf[SF_WR + i*24 + c + 1];
                pr  += tanhap(d[nf][0])*w0 + tanhap(d[nf][1])*w1;
                pr8 += tanhap(d[nf][2])*w0 + tanhap(d[nf][3])*w1;
            }
        }
        pr  += __shfl_xor_sync(0xffffffffu, pr, 1);
        pr  += __shfl_xor_sync(0xffffffffu, pr, 2);
        pr8 += __shfl_xor_sync(0xffffffffu, pr8, 1);
        pr8 += __shfl_xor_sync(0xffffffffu, pr8, 2);
        if ((lane & 3) == 0){
            int e0 = blockIdx.x * BT + rowbase + (lane >> 2);
            if (e0 < n)     out[e0]     = pr  + brv;
            if (e0 + 8 < n) out[e0 + 8] = pr8 + brv;
        }
        __syncwarp();
    }
}

extern "C" void kernel_launch(void* const* d_in, const int* in_sizes, int n_in,
                              void* d_out, int out_size)
{
    const float* x  = (const float*)d_in[0];
    const float* Wf = (const float*)d_in[1];
    const float* bf = (const float*)d_in[2];
    const float* Wm = (const float*)d_in[3];
    const float* bm = (const float*)d_in[4];
    const float* Wu = (const float*)d_in[5];
    const float* bu = (const float*)d_in[6];
    const float* Wr = (const float*)d_in[7];
    const float* br = (const float*)d_in[8];
    float* out = (float*)d_out;

    cudaFuncSetAttribute(mp_kernel, cudaFuncAttributeMaxDynamicSharedMemorySize,
                         SMEM_BYTES);

    const int n = in_sizes[0] / 30;     // B  (x is [B,5,6])
    const int blocks = (n + BT - 1) / BT;
    mp_kernel<<<blocks, BT, SMEM_BYTES>>>(x, Wf, bf, Wm, bm, Wu, bu, Wr, br, out, n);
}

// round 12
// speedup vs baseline: 1.2180x; 1.2180x over previous
#include <cuda_runtime.h>
#include <cuda_fp16.h>

typedef unsigned int u32;
typedef unsigned long long u64;

#define BT 128
#define ROWB 240                 // h-only rows; 240B stride -> conflict-free ldmatrix
// fp32 scalar region (float indices)
#define SF_WF 0                  // 6 x 20
#define SF_BF 120                // 20
#define SF_WR 140                // 5 x 24 (zero-padded)
#define SF_BM 260                // 24
#define SF_BU 284                // 24
#define SF_BR 308
// fp16 B matrices, byte offsets ([32][24] each, rows 18-31 zero)
#define WM1_OFF 1248
#define WM2_OFF (WM1_OFF + 1536)
#define WUH_OFF (WM2_OFF + 1536)
#define WUM_OFF (WUH_OFF + 1536)
#define ACT_OFF (WUM_OFF + 1536)          // 7392 (16B aligned)
#define SMEM_BYTES (ACT_OFF + BT*ROWB)    // 38112 -> 3 CTAs/SM (reg-bound)

static __device__ __forceinline__ u64 dup2(float v){
    u64 r; asm("mov.b64 %0, {%1,%1};" : "=l"(r) : "f"(v)); return r;
}
static __device__ __forceinline__ void upk2(u64 v, float& lo, float& hi){
    asm("mov.b64 {%0,%1}, %2;" : "=f"(lo), "=f"(hi) : "l"(v));
}
static __device__ __forceinline__ u64 fma2(u64 a, u64 b, u64 c){
    u64 d; asm("fma.rn.f32x2 %0, %1, %2, %3;" : "=l"(d) : "l"(a), "l"(b), "l"(c));
    return d;
}
static __device__ __forceinline__ float tanhap(float x){
    float r; asm("tanh.approx.f32 %0, %1;" : "=f"(r) : "f"(x)); return r;
}
static __device__ __forceinline__ void ldrow9(const float* s, int off, u64 w[9]){
    ulonglong2 q0 = *(const ulonglong2*)(s + off);
    ulonglong2 q1 = *(const ulonglong2*)(s + off + 4);
    ulonglong2 q2 = *(const ulonglong2*)(s + off + 8);
    ulonglong2 q3 = *(const ulonglong2*)(s + off + 12);
    w[0]=q0.x; w[1]=q0.y; w[2]=q1.x; w[3]=q1.y;
    w[4]=q2.x; w[5]=q2.y; w[6]=q3.x; w[7]=q3.y;
    w[8] = *(const u64*)(s + off + 16);
}
static __device__ __forceinline__ void ldm4(u32 addr, u32 a[4]){
    asm volatile("ldmatrix.sync.aligned.m8n8.x4.shared.b16 {%0,%1,%2,%3}, [%4];"
        : "=r"(a[0]),"=r"(a[1]),"=r"(a[2]),"=r"(a[3]) : "r"(addr));
}
static __device__ __forceinline__ void mmas(float d[4], const u32 a[4], const u32 b[2]){
    asm volatile("mma.sync.aligned.m16n8k16.row.col.f32.f16.f16.f32 "
        "{%0,%1,%2,%3}, {%4,%5,%6,%7}, {%8,%9}, {%0,%1,%2,%3};"
        : "+f"(d[0]),"+f"(d[1]),"+f"(d[2]),"+f"(d[3])
        : "r"(a[0]),"r"(a[1]),"r"(a[2]),"r"(a[3]), "r"(b[0]),"r"(b[1]));
}
static __device__ __forceinline__ u32 pkh2(float a, float b){
    __half2 h = __floats2half2_rn(a, b);
    return *(u32*)&h;
}
// B fragment (m16n8k16 .col): reg0={B[k0][n],B[k0+1][n]}, reg1={B[k0+8][n],B[k0+9][n]}
static __device__ __forceinline__ void ldbfrag(const __half* W, int ks, int nf, int lane, u32 r[2]){
    int k0 = ks*16 + (lane & 3)*2;
    int nn = nf*8 + (lane >> 2);
    u32 a = __half_as_ushort(W[k0*24 + nn]);
    u32 b = __half_as_ushort(W[(k0+1)*24 + nn]);
    u32 c = __half_as_ushort(W[(k0+8)*24 + nn]);
    u32 d = __half_as_ushort(W[(k0+9)*24 + nn]);
    r[0] = a | (b << 16);
    r[1] = c | (d << 16);
}

__global__ void __launch_bounds__(BT, 3) mp_kernel(
    const float* __restrict__ x,
    const float* __restrict__ Wf, const float* __restrict__ bf,
    const float* __restrict__ Wm, const float* __restrict__ bm,
    const float* __restrict__ Wu, const float* __restrict__ bu,
    const float* __restrict__ Wr, const float* __restrict__ br,
    float* __restrict__ out, int n)
{
    extern __shared__ __align__(16) char smc[];
    float* sf = (float*)smc;
    const int t = threadIdx.x;

    // ---- zero activation region (pads must be finite-zero for mma) ----
    for (int i = t; i < (BT*ROWB)/16; i += BT)
        *(uint4*)(smc + ACT_OFF + i*16) = make_uint4(0,0,0,0);

    // ---- fp32 scalars ----
    for (int k = t; k < 120; k += BT){ int r=k/20, c=k%20; sf[SF_WF+k] = (c<18)? Wf[r*18+c] : 0.f; }
    for (int k = t; k < 20;  k += BT) sf[SF_BF+k] = (k<18)? bf[k] : 0.f;
    for (int k = t; k < 120; k += BT){ int r=k/24, c=k%24; sf[SF_WR+k] = (c<18)? Wr[r*18+c] : 0.f; }
    for (int k = t; k < 24;  k += BT){ sf[SF_BM+k] = (k<18)? bm[k] : 0.f;
                                       sf[SF_BU+k] = (k<18)? bu[k] : 0.f; }
    if (t == 0) sf[SF_BR] = br[0];

    // ---- fp16 B matrices [32][24], rows 18-31 zero ----
    for (int idx = t; idx < 32*24; idx += BT){
        int k = idx/24, nn = idx%24;
        float v1=0.f, v2=0.f, vh=0.f, vm=0.f;
        if (k < 18 && nn < 18){
            v1 = Wm[k*18 + nn];                               // h_i part
            v2 = Wm[(18+k)*18 + nn];                          // h_{i+1} part
            vh = Wu[(18+k)*18 + nn] + Wu[(36+k)*18 + nn];     // folded (U==h)
            vm = Wu[k*18 + nn];
        }
        ((__half*)(smc + WM1_OFF))[idx] = __float2half(v1);
        ((__half*)(smc + WM2_OFF))[idx] = __float2half(v2);
        ((__half*)(smc + WUH_OFF))[idx] = __float2half(vh);
        ((__half*)(smc + WUM_OFF))[idx] = __float2half(vm);
    }
    __syncthreads();

    // ================= layer 1: SIMT fp32, thread = element =================
    int e = blockIdx.x * BT + t;
    if (e >= n) e = n - 1;                    // clamp; no early return (warp-collective mma)
    {
        float xv[30];
        const float2* xb = (const float2*)(x + (long long)e * 30);
        #pragma unroll
        for (int k = 0; k < 15; k++){ float2 v = xb[k]; xv[2*k]=v.x; xv[2*k+1]=v.y; }

        u64 acc[5][9];
        {
            u64 bb[9]; ldrow9(sf, SF_BF, bb);
            #pragma unroll
            for (int p = 0; p < 9; p++){
                #pragma unroll
                for (int i = 0; i < 5; i++) acc[i][p] = bb[p];
            }
        }
        #pragma unroll
        for (int f = 0; f < 6; f++){
            u64 w[9]; ldrow9(sf, SF_WF + f*20, w);
            #pragma unroll
            for (int i = 0; i < 5; i++){
                u64 a = dup2(xv[i*6 + f]);
                #pragma unroll
                for (int p = 0; p < 9; p++) acc[i][p] = fma2(a, w[p], acc[i][p]);
            }
        }
        char* row = smc + ACT_OFF + t*ROWB;
        #pragma unroll
        for (int i = 0; i < 5; i++){
            u32 hp[9];
            #pragma unroll
            for (int p = 0; p < 9; p++){
                float lo, hi; upk2(acc[i][p], lo, hi);
                hp[p] = pkh2(tanhap(lo), tanhap(hi));
            }
            *(uint4*)(row + i*48)      = make_uint4(hp[0],hp[1],hp[2],hp[3]);
            *(uint4*)(row + i*48 + 16) = make_uint4(hp[4],hp[5],hp[6],hp[7]);
            *(u32*) (row + i*48 + 32)  = hp[8];
        }
    }
    __syncwarp();

    // ================= MMA phase: warp = 2 tiles of 16 elements =================
    const int lane = t & 31;
    const int w    = t >> 5;

    u32 Bm1[2][3][2], Bm2[2][3][2], Bh[2][3][2], Bu2[2][3][2];
    {
        const __half* W1 = (const __half*)(smc + WM1_OFF);
        const __half* W2 = (const __half*)(smc + WM2_OFF);
        const __half* WH = (const __half*)(smc + WUH_OFF);
        const __half* WM = (const __half*)(smc + WUM_OFF);
        #pragma unroll
        for (int ks = 0; ks < 2; ks++)
            #pragma unroll
            for (int nf = 0; nf < 3; nf++){
                ldbfrag(W1, ks, nf, lane, Bm1[ks][nf]);
                ldbfrag(W2, ks, nf, lane, Bm2[ks][nf]);
                ldbfrag(WH, ks, nf, lane, Bh[ks][nf]);
                ldbfrag(WM, ks, nf, lane, Bu2[ks][nf]);
            }
    }
    float bmv[3][2], buv[3][2];
    #pragma unroll
    for (int nf = 0; nf < 3; nf++){
        int c = nf*8 + (lane & 3)*2;
        bmv[nf][0] = sf[SF_BM + c]; bmv[nf][1] = sf[SF_BM + c + 1];
        buv[nf][0] = sf[SF_BU + c]; buv[nf][1] = sf[SF_BU + c + 1];
    }
    const float brv = sf[SF_BR];

    const u32 smem_base = (u32)__cvta_generic_to_shared(smc);
    const int lrow = lane & 15;
    const int lcol = (lane >> 4) << 4;

    #pragma unroll
    for (int tl = 0; tl < 2; tl++){
        const int rowbase = w*32 + tl*16;
        u32 ab = smem_base + ACT_OFF + rowbase*ROWB + lrow*ROWB + lcol;

        // compute M fragment for edge i: tanh(h_i@Wm1 + h_{i+1}@Wm2 + bm),
        // packed directly into A-fragment registers Mf[6]
        // (Mf[0..3] = k0-15 A frag; Mf[4..5] = k16-23 half-frag)
        auto computeM = [&](int i, u32 Mf[6]){
            const int ip = (i + 1) % 5;
            u32 a0[4], a1[4], b0[4], b1[4];
            ldm4(ab + i*48,       a0);
            ldm4(ab + i*48  + 32, a1);
            ldm4(ab + ip*48,      b0);
            ldm4(ab + ip*48 + 32, b1);
            float d[3][4];
            #pragma unroll
            for (int nf = 0; nf < 3; nf++){
                d[nf][0]=bmv[nf][0]; d[nf][1]=bmv[nf][1];
                d[nf][2]=bmv[nf][0]; d[nf][3]=bmv[nf][1];
                mmas(d[nf], a0, Bm1[0][nf]);
                mmas(d[nf], a1, Bm1[1][nf]);
                mmas(d[nf], b0, Bm2[0][nf]);
                mmas(d[nf], b1, Bm2[1][nf]);
            }
            // D(m16n8) -> A-fragment (f16) layout identity (FA trick)
            Mf[0] = pkh2(tanhap(d[0][0]), tanhap(d[0][1]));  // rows g,   k0-7
            Mf[1] = pkh2(tanhap(d[0][2]), tanhap(d[0][3]));  // rows g+8, k0-7
            Mf[2] = pkh2(tanhap(d[1][0]), tanhap(d[1][1]));  // rows g,   k8-15
            Mf[3] = pkh2(tanhap(d[1][2]), tanhap(d[1][3]));  // rows g+8, k8-15
            Mf[4] = pkh2(tanhap(d[2][0]), tanhap(d[2][1]));  // rows g,   k16-23
            Mf[5] = pkh2(tanhap(d[2][2]), tanhap(d[2][3]));  // rows g+8, k16-23
        };

        u32 Mf[6];
        computeM(4, Mf);                      // M_4 (consumed by U_0)

        float pr = 0.f, pr8 = 0.f;
        #pragma unroll
        for (int i = 0; i < 5; i++){
            // ---- U_i = tanh(M_{i-1}@WuM + h_i@WuH + bu) ----
            u32 h0[4], h1[4];
            ldm4(ab + i*48,      h0);
            ldm4(ab + i*48 + 32, h1);
            u32 mA[4] = {Mf[0], Mf[1], Mf[2], Mf[3]};
            u32 mB[4] = {Mf[4], Mf[5], 0u, 0u};
            float d[3][4];
            #pragma unroll
            for (int nf = 0; nf < 3; nf++){
                d[nf][0]=buv[nf][0]; d[nf][1]=buv[nf][1];
                d[nf][2]=buv[nf][0]; d[nf][3]=buv[nf][1];
                mmas(d[nf], h0, Bh[0][nf]);
                mmas(d[nf], h1, Bh[1][nf]);
                mmas(d[nf], mA, Bu2[0][nf]);
                mmas(d[nf], mB, Bu2[1][nf]);
            }
            #pragma unroll
            for (int nf = 0; nf < 3; nf++){
                int c = nf*8 + (lane & 3)*2;
                float w0 = sf[SF_WR + i*24 + c];
                float w1 = sf[SF_WR + i*24 + c + 1];
                pr  += tanhap(d[nf][0])*w0 + tanhap(d[nf][1])*w1;
                pr8 += tanhap(d[nf][2])*w0 + tanhap(d[nf][3])*w1;
            }
            if (i < 4) computeM(i, Mf);       // M_i feeds U_{i+1}
        }

        pr  += __shfl_xor_sync(0xffffffffu, pr, 1);
        pr  += __shfl_xor_sync(0xffffffffu, pr, 2);
        pr8 += __shfl_xor_sync(0xffffffffu, pr8, 1);
        pr8 += __shfl_xor_sync(0xffffffffu, pr8, 2);
        if ((lane & 3) == 0){
            int e0 = blockIdx.x * BT + rowbase + (lane >> 2);
            if (e0 < n)     out[e0]     = pr  + brv;
            if (e0 + 8 < n) out[e0 + 8] = pr8 + brv;
        }
    }
}

extern "C" void kernel_launch(void* const* d_in, const int* in_sizes, int n_in,
                              void* d_out, int out_size)
{
    const float* x  = (const float*)d_in[0];
    const float* Wf = (const float*)d_in[1];
    const float* bf = (const float*)d_in[2];
    const float* Wm = (const float*)d_in[3];
    const float* bm = (const float*)d_in[4];
    const float* Wu = (const float*)d_in[5];
    const float* bu = (const float*)d_in[6];
    const float* Wr = (const float*)d_in[7];
    const float* br = (const float*)d_in[8];
    float* out = (float*)d_out;

    cudaFuncSetAttribute(mp_kernel, cudaFuncAttributeMaxDynamicSharedMemorySize,
                         SMEM_BYTES);

    const int n = in_sizes[0] / 30;     // B  (x is [B,5,6])
    const int blocks = (n + BT - 1) / BT;
    mp_kernel<<<blocks, BT, SMEM_BYTES>>>(x, Wf, bf, Wm, bm, Wu, bu, Wr, br, out, n);
}

// round 13
// speedup vs baseline: 1.3515x; 1.1096x over previous
#include <cuda_runtime.h>
#include <cuda_fp16.h>

typedef unsigned int u32;
typedef unsigned long long u64;

#define BT 128
#define ROWB 240                 // h-only rows; 240B stride -> conflict-free ldmatrix
// fp32 scalar region (float indices)
#define SF_WF 0                  // 6 x 20
#define SF_BF 120                // 20
#define SF_WR 140                // 5 x 24 (zero-padded)
#define SF_BM 260                // 24
#define SF_BU 284                // 24
#define SF_BR 308
// fp16 B matrices, byte offsets ([32][24] each, rows 18-31 zero)
#define WM1_OFF 1248
#define WM2_OFF (WM1_OFF + 1536)
#define WUH_OFF (WM2_OFF + 1536)
#define WUM_OFF (WUH_OFF + 1536)
#define ACT_OFF (WUM_OFF + 1536)          // 7392 (16B aligned)
#define SMEM_BYTES (ACT_OFF + BT*ROWB)    // 38112 -> 4 CTAs/SM (reg-capped 128)

static __device__ __forceinline__ u64 dup2(float v){
    u64 r; asm("mov.b64 %0, {%1,%1};" : "=l"(r) : "f"(v)); return r;
}
static __device__ __forceinline__ void upk2(u64 v, float& lo, float& hi){
    asm("mov.b64 {%0,%1}, %2;" : "=f"(lo), "=f"(hi) : "l"(v));
}
static __device__ __forceinline__ u64 fma2(u64 a, u64 b, u64 c){
    u64 d; asm("fma.rn.f32x2 %0, %1, %2, %3;" : "=l"(d) : "l"(a), "l"(b), "l"(c));
    return d;
}
static __device__ __forceinline__ float tanhap(float x){
    float r; asm("tanh.approx.f32 %0, %1;" : "=f"(r) : "f"(x)); return r;
}
// pairs 0..3 (floats 0..7): 2x LDS.128
static __device__ __forceinline__ void ldrowA(const float* s, int off, u64 w[4]){
    ulonglong2 q0 = *(const ulonglong2*)(s + off);
    ulonglong2 q1 = *(const ulonglong2*)(s + off + 4);
    w[0]=q0.x; w[1]=q0.y; w[2]=q1.x; w[3]=q1.y;
}
// pairs 4..8 (floats 8..17): 2x LDS.128 + 1x LDS.64
static __device__ __forceinline__ void ldrowB(const float* s, int off, u64 w[5]){
    ulonglong2 q0 = *(const ulonglong2*)(s + off + 8);
    ulonglong2 q1 = *(const ulonglong2*)(s + off + 12);
    w[0]=q0.x; w[1]=q0.y; w[2]=q1.x; w[3]=q1.y;
    w[4] = *(const u64*)(s + off + 16);
}
static __device__ __forceinline__ void ldm4(u32 addr, u32 a[4]){
    asm volatile("ldmatrix.sync.aligned.m8n8.x4.shared.b16 {%0,%1,%2,%3}, [%4];"
        : "=r"(a[0]),"=r"(a[1]),"=r"(a[2]),"=r"(a[3]) : "r"(addr));
}
static __device__ __forceinline__ void mmas(float d[4], const u32 a[4], const u32 b[2]){
    asm volatile("mma.sync.aligned.m16n8k16.row.col.f32.f16.f16.f32 "
        "{%0,%1,%2,%3}, {%4,%5,%6,%7}, {%8,%9}, {%0,%1,%2,%3};"
        : "+f"(d[0]),"+f"(d[1]),"+f"(d[2]),"+f"(d[3])
        : "r"(a[0]),"r"(a[1]),"r"(a[2]),"r"(a[3]), "r"(b[0]),"r"(b[1]));
}
static __device__ __forceinline__ u32 pkh2(float a, float b){
    __half2 h = __floats2half2_rn(a, b);
    return *(u32*)&h;
}
// B fragment (m16n8k16 .col): reg0={B[k0][n],B[k0+1][n]}, reg1={B[k0+8][n],B[k0+9][n]}
static __device__ __forceinline__ void ldbfrag(const __half* W, int ks, int nf, int lane, u32 r[2]){
    int k0 = ks*16 + (lane & 3)*2;
    int nn = nf*8 + (lane >> 2);
    u32 a = __half_as_ushort(W[k0*24 + nn]);
    u32 b = __half_as_ushort(W[(k0+1)*24 + nn]);
    u32 c = __half_as_ushort(W[(k0+8)*24 + nn]);
    u32 d = __half_as_ushort(W[(k0+9)*24 + nn]);
    r[0] = a | (b << 16);
    r[1] = c | (d << 16);
}

__global__ void __launch_bounds__(BT, 4) mp_kernel(
    const float* __restrict__ x,
    const float* __restrict__ Wf, const float* __restrict__ bf,
    const float* __restrict__ Wm, const float* __restrict__ bm,
    const float* __restrict__ Wu, const float* __restrict__ bu,
    const float* __restrict__ Wr, const float* __restrict__ br,
    float* __restrict__ out, int n)
{
    extern __shared__ __align__(16) char smc[];
    float* sf = (float*)smc;
    const int t = threadIdx.x;

    // ---- zero activation region (pads must be finite-zero for mma) ----
    for (int i = t; i < (BT*ROWB)/16; i += BT)
        *(uint4*)(smc + ACT_OFF + i*16) = make_uint4(0,0,0,0);

    // ---- fp32 scalars ----
    for (int k = t; k < 120; k += BT){ int r=k/20, c=k%20; sf[SF_WF+k] = (c<18)? Wf[r*18+c] : 0.f; }
    for (int k = t; k < 20;  k += BT) sf[SF_BF+k] = (k<18)? bf[k] : 0.f;
    for (int k = t; k < 120; k += BT){ int r=k/24, c=k%24; sf[SF_WR+k] = (c<18)? Wr[r*18+c] : 0.f; }
    for (int k = t; k < 24;  k += BT){ sf[SF_BM+k] = (k<18)? bm[k] : 0.f;
                                       sf[SF_BU+k] = (k<18)? bu[k] : 0.f; }
    if (t == 0) sf[SF_BR] = br[0];

    // ---- fp16 B matrices [32][24], rows 18-31 zero ----
    for (int idx = t; idx < 32*24; idx += BT){
        int k = idx/24, nn = idx%24;
        float v1=0.f, v2=0.f, vh=0.f, vm=0.f;
        if (k < 18 && nn < 18){
            v1 = Wm[k*18 + nn];                               // h_i part
            v2 = Wm[(18+k)*18 + nn];                          // h_{i+1} part
            vh = Wu[(18+k)*18 + nn] + Wu[(36+k)*18 + nn];     // folded (U==h)
            vm = Wu[k*18 + nn];
        }
        ((__half*)(smc + WM1_OFF))[idx] = __float2half(v1);
        ((__half*)(smc + WM2_OFF))[idx] = __float2half(v2);
        ((__half*)(smc + WUH_OFF))[idx] = __float2half(vh);
        ((__half*)(smc + WUM_OFF))[idx] = __float2half(vm);
    }
    __syncthreads();

    // ================= layer 1: SIMT fp32, thread = element, 2 channel passes =================
    int e = blockIdx.x * BT + t;
    if (e >= n) e = n - 1;                    // clamp; no early return (warp-collective mma)
    {
        float xv[30];
        const float2* xb = (const float2*)(x + (long long)e * 30);
        #pragma unroll
        for (int k = 0; k < 15; k++){ float2 v = xb[k]; xv[2*k]=v.x; xv[2*k+1]=v.y; }

        char* row = smc + ACT_OFF + t*ROWB;

        // ---- pass A: channel pairs 0..3 (channels 0-7) ----
        {
            u64 acc[5][4];
            {
                u64 bb[4]; ldrowA(sf, SF_BF, bb);
                #pragma unroll
                for (int p = 0; p < 4; p++){
                    #pragma unroll
                    for (int i = 0; i < 5; i++) acc[i][p] = bb[p];
                }
            }
            #pragma unroll
            for (int f = 0; f < 6; f++){
                u64 w[4]; ldrowA(sf, SF_WF + f*20, w);
                #pragma unroll
                for (int i = 0; i < 5; i++){
                    u64 a = dup2(xv[i*6 + f]);
                    #pragma unroll
                    for (int p = 0; p < 4; p++) acc[i][p] = fma2(a, w[p], acc[i][p]);
                }
            }
            #pragma unroll
            for (int i = 0; i < 5; i++){
                u32 hp[4];
                #pragma unroll
                for (int p = 0; p < 4; p++){
                    float lo, hi; upk2(acc[i][p], lo, hi);
                    hp[p] = pkh2(tanhap(lo), tanhap(hi));
                }
                *(uint4*)(row + i*48) = make_uint4(hp[0],hp[1],hp[2],hp[3]);
            }
        }
        // ---- pass B: channel pairs 4..8 (channels 8-17) ----
        {
            u64 acc[5][5];
            {
                u64 bb[5]; ldrowB(sf, SF_BF, bb);
                #pragma unroll
                for (int p = 0; p < 5; p++){
                    #pragma unroll
                    for (int i = 0; i < 5; i++) acc[i][p] = bb[p];
                }
            }
            #pragma unroll
            for (int f = 0; f < 6; f++){
                u64 w[5]; ldrowB(sf, SF_WF + f*20, w);
                #pragma unroll
                for (int i = 0; i < 5; i++){
                    u64 a = dup2(xv[i*6 + f]);
                    #pragma unroll
                    for (int p = 0; p < 5; p++) acc[i][p] = fma2(a, w[p], acc[i][p]);
                }
            }
            #pragma unroll
            for (int i = 0; i < 5; i++){
                u32 hp[5];
                #pragma unroll
                for (int p = 0; p < 5; p++){
                    float lo, hi; upk2(acc[i][p], lo, hi);
                    hp[p] = pkh2(tanhap(lo), tanhap(hi));
                }
                *(uint4*)(row + i*48 + 16) = make_uint4(hp[0],hp[1],hp[2],hp[3]);
                *(u32*) (row + i*48 + 32)  = hp[4];
            }
        }
    }
    __syncwarp();

    // ================= MMA phase: warp = 2 tiles of 16 elements =================
    const int lane = t & 31;
    const int w    = t >> 5;

    u32 Bm1[2][3][2], Bm2[2][3][2], Bh[2][3][2], Bu2[2][3][2];
    {
        const __half* W1 = (const __half*)(smc + WM1_OFF);
        const __half* W2 = (const __half*)(smc + WM2_OFF);
        const __half* WH = (const __half*)(smc + WUH_OFF);
        const __half* WM = (const __half*)(smc + WUM_OFF);
        #pragma unroll
        for (int ks = 0; ks < 2; ks++)
            #pragma unroll
            for (int nf = 0; nf < 3; nf++){
                ldbfrag(W1, ks, nf, lane, Bm1[ks][nf]);
                ldbfrag(W2, ks, nf, lane, Bm2[ks][nf]);
                ldbfrag(WH, ks, nf, lane, Bh[ks][nf]);
                ldbfrag(WM, ks, nf, lane, Bu2[ks][nf]);
            }
    }
    float bmv[3][2], buv[3][2];
    #pragma unroll
    for (int nf = 0; nf < 3; nf++){
        int c = nf*8 + (lane & 3)*2;
        bmv[nf][0] = sf[SF_BM + c]; bmv[nf][1] = sf[SF_BM + c + 1];
        buv[nf][0] = sf[SF_BU + c]; buv[nf][1] = sf[SF_BU + c + 1];
    }
    const float brv = sf[SF_BR];

    const u32 smem_base = (u32)__cvta_generic_to_shared(smc);
    const int lrow = lane & 15;
    const int lcol = (lane >> 4) << 4;

    #pragma unroll
    for (int tl = 0; tl < 2; tl++){
        const int rowbase = w*32 + tl*16;
        u32 ab = smem_base + ACT_OFF + rowbase*ROWB + lrow*ROWB + lcol;

        // M_i = tanh(h_i@Wm1 + h_{i+1}@Wm2 + bm) packed straight into A-fragment regs
        auto computeM = [&](int i, u32 Mf[6]){
            const int ip = (i + 1) % 5;
            u32 a0[4], a1[4], b0[4], b1[4];
            ldm4(ab + i*48,       a0);
            ldm4(ab + i*48  + 32, a1);
            ldm4(ab + ip*48,      b0);
            ldm4(ab + ip*48 + 32, b1);
            float d[3][4];
            #pragma unroll
            for (int nf = 0; nf < 3; nf++){
                d[nf][0]=bmv[nf][0]; d[nf][1]=bmv[nf][1];
                d[nf][2]=bmv[nf][0]; d[nf][3]=bmv[nf][1];
                mmas(d[nf], a0, Bm1[0][nf]);
                mmas(d[nf], a1, Bm1[1][nf]);
                mmas(d[nf], b0, Bm2[0][nf]);
                mmas(d[nf], b1, Bm2[1][nf]);
            }
            Mf[0] = pkh2(tanhap(d[0][0]), tanhap(d[0][1]));
            Mf[1] = pkh2(tanhap(d[0][2]), tanhap(d[0][3]));
            Mf[2] = pkh2(tanhap(d[1][0]), tanhap(d[1][1]));
            Mf[3] = pkh2(tanhap(d[1][2]), tanhap(d[1][3]));
            Mf[4] = pkh2(tanhap(d[2][0]), tanhap(d[2][1]));
            Mf[5] = pkh2(tanhap(d[2][2]), tanhap(d[2][3]));
        };

        u32 Mf[6];
        computeM(4, Mf);                      // M_4 (consumed by U_0)

        float pr = 0.f, pr8 = 0.f;
        #pragma unroll
        for (int i = 0; i < 5; i++){
            u32 h0[4], h1[4];
            ldm4(ab + i*48,      h0);
            ldm4(ab + i*48 + 32, h1);
            u32 mA[4] = {Mf[0], Mf[1], Mf[2], Mf[3]};
            u32 mB[4] = {Mf[4], Mf[5], 0u, 0u};
            float d[3][4];
            #pragma unroll
            for (int nf = 0; nf < 3; nf++){
                d[nf][0]=buv[nf][0]; d[nf][1]=buv[nf][1];
                d[nf][2]=buv[nf][0]; d[nf][3]=buv[nf][1];
                mmas(d[nf], h0, Bh[0][nf]);
                mmas(d[nf], h1, Bh[1][nf]);
                mmas(d[nf], mA, Bu2[0][nf]);
                mmas(d[nf], mB, Bu2[1][nf]);
            }
            #pragma unroll
            for (int nf = 0; nf < 3; nf++){
                int c = nf*8 + (lane & 3)*2;
                float w0 = sf[SF_WR + i*24 + c];
                float w1 = sf[SF_WR + i*24 + c + 1];
                pr  += tanhap(d[nf][0])*w0 + tanhap(d[nf][1])*w1;
                pr8 += tanhap(d[nf][2])*w0 + tanhap(d[nf][3])*w1;
            }
            if (i < 4) computeM(i, Mf);       // M_i feeds U_{i+1}
        }

        pr  += __shfl_xor_sync(0xffffffffu, pr, 1);
        pr  += __shfl_xor_sync(0xffffffffu, pr, 2);
        pr8 += __shfl_xor_sync(0xffffffffu, pr8, 1);
        pr8 += __shfl_xor_sync(0xffffffffu, pr8, 2);
        if ((lane & 3) == 0){
            int e0 = blockIdx.x * BT + rowbase + (lane >> 2);
            if (e0 < n)     out[e0]     = pr  + brv;
            if (e0 + 8 < n) out[e0 + 8] = pr8 + brv;
        }
    }
}

extern "C" void kernel_launch(void* const* d_in, const int* in_sizes, int n_in,
                              void* d_out, int out_size)
{
    const float* x  = (const float*)d_in[0];
    const float* Wf = (const float*)d_in[1];
    const float* bf = (const float*)d_in[2];
    const float* Wm = (const float*)d_in[3];
    const float* bm = (const float*)d_in[4];
    const float* Wu = (const float*)d_in[5];
    const float* bu = (const float*)d_in[6];
    const float* Wr = (const float*)d_in[7];
    const float* br = (const float*)d_in[8];
    float* out = (float*)d_out;

    cudaFuncSetAttribute(mp_kernel, cudaFuncAttributeMaxDynamicSharedMemorySize,
                         SMEM_BYTES);

    const int n = in_sizes[0] / 30;     // B  (x is [B,5,6])
    const int blocks = (n + BT - 1) / BT;
    mp_kernel<<<blocks, BT, SMEM_BYTES>>>(x, Wf, bf, Wm, bm, Wu, bu, Wr, br, out, n);
}

// round 14
// speedup vs baseline: 1.3526x; 1.0008x over previous
#include <cuda_runtime.h>
#include <cuda_fp16.h>

typedef unsigned int u32;
typedef unsigned long long u64;

#define BT 128
#define ROWB 240                 // h-only rows; 240B stride -> conflict-free ldmatrix
// fp32 scalar region (float indices)
#define SF_WF 0                  // 6 x 20
#define SF_BF 120                // 20
#define SF_WR 140                // 5 x 24 (zero-padded)
#define SF_BM 260                // 24
#define SF_BU 284                // 24
#define SF_BR 308
// fp16 B matrices, byte offsets ([32][24] each, rows 18-31 zero)
#define WM1_OFF 1248
#define WM2_OFF (WM1_OFF + 1536)
#define WUH_OFF (WM2_OFF + 1536)
#define WUM_OFF (WUH_OFF + 1536)
#define ACT_OFF (WUM_OFF + 1536)          // 7392 (16B aligned)
#define SMEM_BYTES (ACT_OFF + BT*ROWB)    // 38112 -> 4 CTAs/SM (reg-capped 128)

static __device__ __forceinline__ u64 dup2(float v){
    u64 r; asm("mov.b64 %0, {%1,%1};" : "=l"(r) : "f"(v)); return r;
}
static __device__ __forceinline__ void upk2(u64 v, float& lo, float& hi){
    asm("mov.b64 {%0,%1}, %2;" : "=f"(lo), "=f"(hi) : "l"(v));
}
static __device__ __forceinline__ u64 fma2(u64 a, u64 b, u64 c){
    u64 d; asm("fma.rn.f32x2 %0, %1, %2, %3;" : "=l"(d) : "l"(a), "l"(b), "l"(c));
    return d;
}
static __device__ __forceinline__ float tanhap(float x){
    float r; asm("tanh.approx.f32 %0, %1;" : "=f"(r) : "f"(x)); return r;
}
// pairs 0..3 (floats 0..7)
static __device__ __forceinline__ void ldrowA(const float* s, int off, u64 w[4]){
    ulonglong2 q0 = *(const ulonglong2*)(s + off);
    ulonglong2 q1 = *(const ulonglong2*)(s + off + 4);
    w[0]=q0.x; w[1]=q0.y; w[2]=q1.x; w[3]=q1.y;
}
// pairs 4..8 (floats 8..17)
static __device__ __forceinline__ void ldrowB(const float* s, int off, u64 w[5]){
    ulonglong2 q0 = *(const ulonglong2*)(s + off + 8);
    ulonglong2 q1 = *(const ulonglong2*)(s + off + 12);
    w[0]=q0.x; w[1]=q0.y; w[2]=q1.x; w[3]=q1.y;
    w[4] = *(const u64*)(s + off + 16);
}
static __device__ __forceinline__ void ldm4(u32 addr, u32 a[4]){
    asm volatile("ldmatrix.sync.aligned.m8n8.x4.shared.b16 {%0,%1,%2,%3}, [%4];"
        : "=r"(a[0]),"=r"(a[1]),"=r"(a[2]),"=r"(a[3]) : "r"(addr));
}
static __device__ __forceinline__ void ldm2(u32 addr, u32 a[2]){
    asm volatile("ldmatrix.sync.aligned.m8n8.x2.shared.b16 {%0,%1}, [%2];"
        : "=r"(a[0]),"=r"(a[1]) : "r"(addr));
}
static __device__ __forceinline__ void mmas(float d[4], const u32 a[4], const u32 b[2]){
    asm volatile("mma.sync.aligned.m16n8k16.row.col.f32.f16.f16.f32 "
        "{%0,%1,%2,%3}, {%4,%5,%6,%7}, {%8,%9}, {%0,%1,%2,%3};"
        : "+f"(d[0]),"+f"(d[1]),"+f"(d[2]),"+f"(d[3])
        : "r"(a[0]),"r"(a[1]),"r"(a[2]),"r"(a[3]), "r"(b[0]),"r"(b[1]));
}
static __device__ __forceinline__ void mmas8(float d[4], const u32 a[2], u32 b){
    asm volatile("mma.sync.aligned.m16n8k8.row.col.f32.f16.f16.f32 "
        "{%0,%1,%2,%3}, {%4,%5}, {%6}, {%0,%1,%2,%3};"
        : "+f"(d[0]),"+f"(d[1]),"+f"(d[2]),"+f"(d[3])
        : "r"(a[0]),"r"(a[1]), "r"(b));
}
static __device__ __forceinline__ u32 pkh2(float a, float b){
    __half2 h = __floats2half2_rn(a, b);
    return *(u32*)&h;
}
// k16 B fragment (.col): reg0={B[k0][n],B[k0+1][n]}, reg1={B[k0+8][n],B[k0+9][n]}
static __device__ __forceinline__ void ldbfrag16(const __half* W, int nf, int lane, u32 r[2]){
    int k0 = (lane & 3)*2;
    int nn = nf*8 + (lane >> 2);
    u32 a = __half_as_ushort(W[k0*24 + nn]);
    u32 b = __half_as_ushort(W[(k0+1)*24 + nn]);
    u32 c = __half_as_ushort(W[(k0+8)*24 + nn]);
    u32 d = __half_as_ushort(W[(k0+9)*24 + nn]);
    r[0] = a | (b << 16);
    r[1] = c | (d << 16);
}
// k8 B fragment over global k rows 16-23
static __device__ __forceinline__ u32 ldbfrag8(const __half* W, int nf, int lane){
    int k0 = 16 + (lane & 3)*2;
    int nn = nf*8 + (lane >> 2);
    return (u32)__half_as_ushort(W[k0*24 + nn])
         | ((u32)__half_as_ushort(W[(k0+1)*24 + nn]) << 16);
}

__global__ void __launch_bounds__(BT, 4) mp_kernel(
    const float* __restrict__ x,
    const float* __restrict__ Wf, const float* __restrict__ bf,
    const float* __restrict__ Wm, const float* __restrict__ bm,
    const float* __restrict__ Wu, const float* __restrict__ bu,
    const float* __restrict__ Wr, const float* __restrict__ br,
    float* __restrict__ out, int n)
{
    extern __shared__ __align__(16) char smc[];
    float* sf = (float*)smc;
    const int t = threadIdx.x;

    // ---- zero activation region (pads must be finite-zero for mma) ----
    for (int i = t; i < (BT*ROWB)/16; i += BT)
        *(uint4*)(smc + ACT_OFF + i*16) = make_uint4(0,0,0,0);

    // ---- fp32 scalars ----
    for (int k = t; k < 120; k += BT){ int r=k/20, c=k%20; sf[SF_WF+k] = (c<18)? Wf[r*18+c] : 0.f; }
    for (int k = t; k < 20;  k += BT) sf[SF_BF+k] = (k<18)? bf[k] : 0.f;
    for (int k = t; k < 120; k += BT){ int r=k/24, c=k%24; sf[SF_WR+k] = (c<18)? Wr[r*18+c] : 0.f; }
    for (int k = t; k < 24;  k += BT){ sf[SF_BM+k] = (k<18)? bm[k] : 0.f;
                                       sf[SF_BU+k] = (k<18)? bu[k] : 0.f; }
    if (t == 0) sf[SF_BR] = br[0];

    // ---- fp16 B matrices [32][24], rows 18-31 zero ----
    for (int idx = t; idx < 32*24; idx += BT){
        int k = idx/24, nn = idx%24;
        float v1=0.f, v2=0.f, vh=0.f, vm=0.f;
        if (k < 18 && nn < 18){
            v1 = Wm[k*18 + nn];                               // h_i part
            v2 = Wm[(18+k)*18 + nn];                          // h_{i+1} part
            vh = Wu[(18+k)*18 + nn] + Wu[(36+k)*18 + nn];     // folded (U==h)
            vm = Wu[k*18 + nn];
        }
        ((__half*)(smc + WM1_OFF))[idx] = __float2half(v1);
        ((__half*)(smc + WM2_OFF))[idx] = __float2half(v2);
        ((__half*)(smc + WUH_OFF))[idx] = __float2half(vh);
        ((__half*)(smc + WUM_OFF))[idx] = __float2half(vm);
    }
    __syncthreads();

    // ================= layer 1: SIMT fp32, thread = element, 2 channel passes =================
    int e = blockIdx.x * BT + t;
    if (e >= n) e = n - 1;                    // clamp; no early return (warp-collective mma)
    {
        float xv[30];
        const float2* xb = (const float2*)(x + (long long)e * 30);
        #pragma unroll
        for (int k = 0; k < 15; k++){ float2 v = xb[k]; xv[2*k]=v.x; xv[2*k+1]=v.y; }

        char* row = smc + ACT_OFF + t*ROWB;

        // ---- pass A: channels 0-7 ----
        {
            u64 acc[5][4];
            {
                u64 bb[4]; ldrowA(sf, SF_BF, bb);
                #pragma unroll
                for (int p = 0; p < 4; p++){
                    #pragma unroll
                    for (int i = 0; i < 5; i++) acc[i][p] = bb[p];
                }
            }
            #pragma unroll
            for (int f = 0; f < 6; f++){
                u64 w[4]; ldrowA(sf, SF_WF + f*20, w);
                #pragma unroll
                for (int i = 0; i < 5; i++){
                    u64 a = dup2(xv[i*6 + f]);
                    #pragma unroll
                    for (int p = 0; p < 4; p++) acc[i][p] = fma2(a, w[p], acc[i][p]);
                }
            }
            #pragma unroll
            for (int i = 0; i < 5; i++){
                u32 hp[4];
                #pragma unroll
                for (int p = 0; p < 4; p++){
                    float lo, hi; upk2(acc[i][p], lo, hi);
                    hp[p] = pkh2(tanhap(lo), tanhap(hi));
                }
                *(uint4*)(row + i*48) = make_uint4(hp[0],hp[1],hp[2],hp[3]);
            }
        }
        // ---- pass B: channels 8-17 ----
        {
            u64 acc[5][5];
            {
                u64 bb[5]; ldrowB(sf, SF_BF, bb);
                #pragma unroll
                for (int p = 0; p < 5; p++){
                    #pragma unroll
                    for (int i = 0; i < 5; i++) acc[i][p] = bb[p];
                }
            }
            #pragma unroll
            for (int f = 0; f < 6; f++){
                u64 w[5]; ldrowB(sf, SF_WF + f*20, w);
                #pragma unroll
                for (int i = 0; i < 5; i++){
                    u64 a = dup2(xv[i*6 + f]);
                    #pragma unroll
                    for (int p = 0; p < 5; p++) acc[i][p] = fma2(a, w[p], acc[i][p]);
                }
            }
            #pragma unroll
            for (int i = 0; i < 5; i++){
                u32 hp[5];
                #pragma unroll
                for (int p = 0; p < 5; p++){
                    float lo, hi; upk2(acc[i][p], lo, hi);
                    hp[p] = pkh2(tanhap(lo), tanhap(hi));
                }
                *(uint4*)(row + i*48 + 16) = make_uint4(hp[0],hp[1],hp[2],hp[3]);
                *(u32*) (row + i*48 + 32)  = hp[4];
            }
        }
    }
    __syncwarp();

    // ================= MMA phase: warp = 2 tiles of 16 elements =================
    const int lane = t & 31;
    const int w    = t >> 5;

    // B fragments: k16 chunk (2 regs) + k8 chunk (1 reg) per n-frag
    u32 Bm1a[3][2], Bm2a[3][2], Bha[3][2], Bua[3][2];
    u32 Bm1b[3],    Bm2b[3],    Bhb[3],    Bub[3];
    {
        const __half* W1 = (const __half*)(smc + WM1_OFF);
        const __half* W2 = (const __half*)(smc + WM2_OFF);
        const __half* WH = (const __half*)(smc + WUH_OFF);
        const __half* WM = (const __half*)(smc + WUM_OFF);
        #pragma unroll
        for (int nf = 0; nf < 3; nf++){
            ldbfrag16(W1, nf, lane, Bm1a[nf]);  Bm1b[nf] = ldbfrag8(W1, nf, lane);
            ldbfrag16(W2, nf, lane, Bm2a[nf]);  Bm2b[nf] = ldbfrag8(W2, nf, lane);
            ldbfrag16(WH, nf, lane, Bha[nf]);   Bhb[nf]  = ldbfrag8(WH, nf, lane);
            ldbfrag16(WM, nf, lane, Bua[nf]);   Bub[nf]  = ldbfrag8(WM, nf, lane);
        }
    }
    float bmv[3][2], buv[3][2];
    #pragma unroll
    for (int nf = 0; nf < 3; nf++){
        int c = nf*8 + (lane & 3)*2;
        bmv[nf][0] = sf[SF_BM + c]; bmv[nf][1] = sf[SF_BM + c + 1];
        buv[nf][0] = sf[SF_BU + c]; buv[nf][1] = sf[SF_BU + c + 1];
    }
    const float brv = sf[SF_BR];

    const u32 smem_base = (u32)__cvta_generic_to_shared(smc);
    const int lrow = lane & 15;
    const int lcol = (lane >> 4) << 4;

    #pragma unroll
    for (int tl = 0; tl < 2; tl++){
        const int rowbase = w*32 + tl*16;
        u32 tb  = smem_base + ACT_OFF + rowbase*ROWB;
        u32 ab  = tb + lrow*ROWB + lcol;          // x4 base (cols 0-15)
        u32 ab2 = tb + lrow*ROWB + 32;            // x2 base (cols 16-23)

        // ---- load all 5 h fragments ONCE; ring runs register-only after this ----
        u32 hf[5][6];
        #pragma unroll
        for (int i = 0; i < 5; i++){
            ldm4(ab  + i*48, &hf[i][0]);
            ldm2(ab2 + i*48, &hf[i][4]);
        }

        // M_i = tanh(h_i@Wm1 + h_{i+1}@Wm2 + bm) packed straight into A-fragment regs
        auto computeM = [&](int i, u32 Mf[6]){
            const int ip = (i + 1) % 5;
            float d[3][4];
            #pragma unroll
            for (int nf = 0; nf < 3; nf++){
                d[nf][0]=bmv[nf][0]; d[nf][1]=bmv[nf][1];
                d[nf][2]=bmv[nf][0]; d[nf][3]=bmv[nf][1];
                mmas (d[nf], &hf[i][0],  Bm1a[nf]);
                mmas8(d[nf], &hf[i][4],  Bm1b[nf]);
                mmas (d[nf], &hf[ip][0], Bm2a[nf]);
                mmas8(d[nf], &hf[ip][4], Bm2b[nf]);
            }
            Mf[0] = pkh2(tanhap(d[0][0]), tanhap(d[0][1]));
            Mf[1] = pkh2(tanhap(d[0][2]), tanhap(d[0][3]));
            Mf[2] = pkh2(tanhap(d[1][0]), tanhap(d[1][1]));
            Mf[3] = pkh2(tanhap(d[1][2]), tanhap(d[1][3]));
            Mf[4] = pkh2(tanhap(d[2][0]), tanhap(d[2][1]));
            Mf[5] = pkh2(tanhap(d[2][2]), tanhap(d[2][3]));
        };

        u32 Mf[6];
        computeM(4, Mf);                      // M_4 (consumed by U_0)

        float pr = 0.f, pr8 = 0.f;
        #pragma unroll
        for (int i = 0; i < 5; i++){
            // ---- U_i = tanh(M_{i-1}@WuM + h_i@WuH + bu) ----
            float d[3][4];
            #pragma unroll
            for (int nf = 0; nf < 3; nf++){
                d[nf][0]=buv[nf][0]; d[nf][1]=buv[nf][1];
                d[nf][2]=buv[nf][0]; d[nf][3]=buv[nf][1];
                mmas (d[nf], &hf[i][0], Bha[nf]);
                mmas8(d[nf], &hf[i][4], Bhb[nf]);
                mmas (d[nf], &Mf[0],    Bua[nf]);
                mmas8(d[nf], &Mf[4],    Bub[nf]);
            }
            #pragma unroll
            for (int nf = 0; nf < 3; nf++){
                int c = nf*8 + (lane & 3)*2;
                float w0 = sf[SF_WR + i*24 + c];
                float w1 = sf[SF_WR + i*24 + c + 1];
                pr  += tanhap(d[nf][0])*w0 + tanhap(d[nf][1])*w1;
                pr8 += tanhap(d[nf][2])*w0 + tanhap(d[nf][3])*w1;
            }
            if (i < 4) computeM(i, Mf);       // M_i feeds U_{i+1}
        }

        pr  += __shfl_xor_sync(0xffffffffu, pr, 1);
        pr  += __shfl_xor_sync(0xffffffffu, pr, 2);
        pr8 += __shfl_xor_sync(0xffffffffu, pr8, 1);
        pr8 += __shfl_xor_sync(0xffffffffu, pr8, 2);
        if ((lane & 3) == 0){
            int e0 = blockIdx.x * BT + rowbase + (lane >> 2);
            if (e0 < n)     out[e0]     = pr  + brv;
            if (e0 + 8 < n) out[e0 + 8] = pr8 + brv;
        }
    }
}

extern "C" void kernel_launch(void* const* d_in, const int* in_sizes, int n_in,
                              void* d_out, int out_size)
{
    const float* x  = (const float*)d_in[0];
    const float* Wf = (const float*)d_in[1];
    const float* bf = (const float*)d_in[2];
    const float* Wm = (const float*)d_in[3];
    const float* bm = (const float*)d_in[4];
    const float* Wu = (const float*)d_in[5];
    const float* bu = (const float*)d_in[6];
    const float* Wr = (const float*)d_in[7];
    const float* br = (const float*)d_in[8];
    float* out = (float*)d_out;

    cudaFuncSetAttribute(mp_kernel, cudaFuncAttributeMaxDynamicSharedMemorySize,
                         SMEM_BYTES);

    const int n = in_sizes[0] / 30;     // B  (x is [B,5,6])
    const int blocks = (n + BT - 1) / BT;
    mp_kernel<<<blocks, BT, SMEM_BYTES>>>(x, Wf, bf, Wm, bm, Wu, bu, Wr, br, out, n);
}